// round 14
// baseline (speedup 1.0000x reference)
#include <cuda_runtime.h>
#include <cstdint>

#define TT 4096
#define BB 128
#define CC 46
#define LL 43
#define NCH 8                 /* chunks (of 16 timesteps per warp) per block */
#define CHB 8                 /* blocks per batch; block covers 512 ts, warp 128 */
#define NINF (-3.4e38f)
#define LN2F 0.6931471805599453f

// ---------------- scratch (static device globals; no allocation) ----------------
__device__ float4 g_cmats[BB * CHB];
__device__ int    g_cexp[BB * CHB];
__device__ float  g_numpart[BB * CHB];

// ---------------- scaled-probability semiring matrix ----------------
// value = 2^e * P, P 2x2 row-major: x=00, y=01, z=10, w=11, max entry in [1,2).
struct SMat { float4 p; int e; };

// C = A (later) * B (earlier): 8 FFMA + integer exponent renorm (no MUFU).
__device__ __forceinline__ SMat smul(const SMat A, const SMat B) {
    SMat C;
    C.p.x = fmaf(A.p.x, B.p.x, A.p.y * B.p.z);
    C.p.y = fmaf(A.p.x, B.p.y, A.p.y * B.p.w);
    C.p.z = fmaf(A.p.z, B.p.x, A.p.w * B.p.z);
    C.p.w = fmaf(A.p.z, B.p.y, A.p.w * B.p.w);
    float mx = fmaxf(fmaxf(C.p.x, C.p.y), fmaxf(C.p.z, C.p.w));
    int   k  = (__float_as_int(mx) >> 23) & 255;         // biased exponent of mx
    float r  = __int_as_float((254 - k) << 23);          // exact 2^(127-k)
    C.p.x *= r; C.p.y *= r; C.p.z *= r; C.p.w *= r;
    C.e = A.e + B.e + (k - 127);
    return C;
}

__device__ __forceinline__ SMat shfl_down_m(const SMat v, int s, int w) {
    SMat r;
    r.p.x = __shfl_down_sync(0xffffffffu, v.p.x, s, w);
    r.p.y = __shfl_down_sync(0xffffffffu, v.p.y, s, w);
    r.p.z = __shfl_down_sync(0xffffffffu, v.p.z, s, w);
    r.p.w = __shfl_down_sync(0xffffffffu, v.p.w, s, w);
    r.e   = __shfl_down_sync(0xffffffffu, v.e,   s, w);
    return r;
}

__device__ __forceinline__ void cp16(uint32_t dst, const float4* src) {
    asm volatile("cp.async.cg.shared.global [%0], [%1], 16;\n" :: "r"(dst), "l"(src));
}

// ---------------- k1: half-row warp-private pipelined kernel ----------------
// grid (CHB, BB), block 128 threads (4 warps). Warp w owns [t0+128w, t0+128w+128),
// processed as NCH chunks of 16 timesteps; lane pair (2r,2r+1) shares row r.
__global__ void __launch_bounds__(128) k1_main(
    const float* __restrict__ lp,
    const float* __restrict__ dp,
    const int* __restrict__ lens,
    const int* __restrict__ labels)
{
    __shared__ float  tiles[2][64 * CC];    // 2 x 11776 B; warp w rows [16w,16w+16)
    __shared__ float2 wab[CC];              // (w0, w1) per column; cols 0,2 zeroed
    __shared__ float  scs[2];               // [0]=exp(s_0I), [1]=exp(s_1I)
    __shared__ float4 warpP[4];
    __shared__ int    warpE[4];
    __shared__ float  warpT[4];

    const int tid  = threadIdx.x;
    const int lane = tid & 31;
    const int wid  = tid >> 5;
    const int half = lane & 1;
    const int row  = lane >> 1;             // 0..15 within chunk
    const int b    = blockIdx.y;
    const int t0   = blockIdx.x * (128 * NCH / 2);   // 512 ts per block

    // warp w's 128-timestep segment: 128*46/4 = 1472 float4 per warp
    const float4* __restrict__ base4 =
        (const float4*)(lp + ((size_t)b * TT + t0) * CC) + (size_t)wid * 1472;
    // per-warp buffer segment: 184 float4 (16 rows x 184 B)
    const uint32_t smA = (uint32_t)__cvta_generic_to_shared(&tiles[0][0]) + wid * 184 * 16;
    const uint32_t smB = (uint32_t)__cvta_generic_to_shared(&tiles[1][0]) + wid * 184 * 16;

    // --- warp-local prefetch of chunk 0 (184 float4) ---
#pragma unroll
    for (int k = 0; k < 6; k++) {
        int i = lane + 32 * k;
        if (i < 184) cp16(smA + i * 16, base4 + i);
    }
    asm volatile("cp.async.commit_group;\n");

    // --- warp 0: params (overlaps prefetch latency) ---
    if (wid == 0) {
        float a  = dp[lane];
        float bb = (lane + 32 < CC) ? dp[lane + 32] : NINF;
        float m = fmaxf(a, bb);
#pragma unroll
        for (int o = 16; o; o >>= 1) m = fmaxf(m, __shfl_xor_sync(0xffffffffu, m, o));
        float s = __expf(a - m) + __expf(bb - m);
#pragma unroll
        for (int o = 16; o; o >>= 1) s += __shfl_xor_sync(0xffffffffu, s, o);
        const float lz0 = m + __logf(s);
        float a1 = (lane < LL + 1) ? dp[CC + lane] : NINF;
        float b1 = (lane + 32 < LL + 1) ? dp[CC + lane + 32] : NINF;
        float m1 = fmaxf(a1, b1);
#pragma unroll
        for (int o = 16; o; o >>= 1) m1 = fmaxf(m1, __shfl_xor_sync(0xffffffffu, m1, o));
        float s1 = __expf(a1 - m1) + __expf(b1 - m1);
#pragma unroll
        for (int o = 16; o; o >>= 1) s1 += __shfl_xor_sync(0xffffffffu, s1, o);
        const float lz1 = m1 + __logf(s1);
#pragma unroll
        for (int c = lane; c < CC; c += 32) {
            float w0 = 0.f, w1 = 0.f;
            if (c == 1) w0 = __expf(dp[0] - lz0);          // exp(s_O): folds s_O+lp1 into S0
            if (c >= 3) {
                w0 = __expf(dp[c - 2] - lz0);              // exp(s0_lab)
                w1 = __expf(dp[CC + c - 2] - lz1);         // exp(s1_lab)
            }
            wab[c] = make_float2(w0, w1);
        }
        if (lane == 0) {
            scs[0] = __expf(dp[LL + 1] - lz0);   // exp(s_0I)
            scs[1] = __expf(dp[CC] - lz1);       // exp(s_1I)
        }
    }
    __syncthreads();   // wab/scs visible; no more block barriers until the end

    // release the dependent k2 launch as early as possible (PDL)
    cudaTriggerProgrammaticLaunchCompletion();

    const int len = lens[b];
    const float k0 = scs[0], k1c = scs[1];
    float tok_acc = 0.f;
    SMat run;   // meaningful on lane 0 of each warp

    for (int c = 0; c < NCH; c++) {
        if (c + 1 < NCH) {
            const uint32_t dsm = ((c + 1) & 1) ? smB : smA;
            const float4* src = base4 + (size_t)(c + 1) * 184;
#pragma unroll
            for (int k = 0; k < 6; k++) {
                int i = lane + 32 * k;
                if (i < 184) cp16(dsm + i * 16, src + i);
            }
            asm volatile("cp.async.commit_group;\n");
            asm volatile("cp.async.wait_group 1;\n");
        } else {
            asm volatile("cp.async.wait_group 0;\n");
        }
        __syncwarp();   // warp-local buffer ownership

        const float* rowp = tiles[c & 1] + (wid * 16 + row) * CC;
        const int t = t0 + wid * 128 + c * 16 + row;
        const bool valid = t < len;

        // ---- half-row evaluation: even lane cols 0..22, odd lane cols 23..45 ----
        float S0 = 0.f, S1 = 0.f, e2 = 0.f;
        if (half == 0) {
            const float2* rp2 = (const float2*)rowp;        // rowp 8B-aligned (46*r even)
#pragma unroll
            for (int i = 0; i < 11; i++) {                  // cols 0..21
                float2 q = rp2[i];
                float ex = __expf(q.x);
                float ey = __expf(q.y);
                if (i == 1) e2 = ex;                        // exp(lp[2])
                float2 wA = wab[2 * i];
                float2 wB = wab[2 * i + 1];
                S0 = fmaf(ex, wA.x, S0); S1 = fmaf(ex, wA.y, S1);
                S0 = fmaf(ey, wB.x, S0); S1 = fmaf(ey, wB.y, S1);
            }
            {   // col 22
                float e = __expf(rowp[22]);
                float2 w = wab[22];
                S0 = fmaf(e, w.x, S0); S1 = fmaf(e, w.y, S1);
            }
        } else {
            {   // col 23 (scalar; word 23 is 4B-aligned only)
                float e = __expf(rowp[23]);
                float2 w = wab[23];
                S0 = fmaf(e, w.x, S0); S1 = fmaf(e, w.y, S1);
            }
            const float2* rp2 = (const float2*)(rowp + 24); // word 24: 8B-aligned
#pragma unroll
            for (int i = 0; i < 11; i++) {                  // cols 24..45
                float2 q = rp2[i];
                float ex = __expf(q.x);
                float ey = __expf(q.y);
                float2 wA = wab[24 + 2 * i];
                float2 wB = wab[25 + 2 * i];
                S0 = fmaf(ex, wA.x, S0); S1 = fmaf(ex, wA.y, S1);
                S0 = fmaf(ey, wB.x, S0); S1 = fmaf(ey, wB.y, S1);
            }
        }
        // pair combine: even lane accumulates odd lane's partial sums
        float oS0 = __shfl_down_sync(0xffffffffu, S0, 1);
        float oS1 = __shfl_down_sync(0xffffffffu, S1, 1);

        SMat M;
        M.p = make_float4(1.f, 0.f, 0.f, 1.f);   // identity (odd lanes & invalid rows)
        M.e = 0;
        if (half == 0) {
            const int lab = labels[(size_t)b * TT + t];
            tok_acc += valid ? rowp[lab] : 0.f;
            if (valid) {
                M.p = make_float4(S0 + oS0, S1 + oS1, e2 * k0, e2 * k1c);
            }
        }

        // tree fold over 16 even-lane matrices (strides 2..16), MUFU-free
#pragma unroll
        for (int s = 2; s < 32; s <<= 1) {
            SMat o = shfl_down_m(M, s, 32);
            if ((lane & (2 * s - 1)) == 0) M = smul(o, M);
        }
        run = (c == 0) ? M : smul(M, run);   // valid on lane 0
    }

    // token warp sum; publish per-warp results
#pragma unroll
    for (int o = 16; o; o >>= 1) tok_acc += __shfl_xor_sync(0xffffffffu, tok_acc, o);
    if (lane == 0) { warpP[wid] = run.p; warpE[wid] = run.e; warpT[wid] = tok_acc; }
    __syncthreads();

    if (wid == 0) {
        SMat A;
        if (lane < 4) { A.p = warpP[lane]; A.e = warpE[lane]; }
        else          { A.p = make_float4(1.f, 0.f, 0.f, 1.f); A.e = 0; }
#pragma unroll
        for (int s = 1; s < 4; s <<= 1) {
            SMat o = shfl_down_m(A, s, 4);
            if ((lane & (2 * s - 1)) == 0 && lane + s < 4) A = smul(o, A);
        }
        if (lane == 0) {
            const int slot = b * CHB + blockIdx.x;
            g_cmats[slot]   = A.p;
            g_cexp[slot]    = A.e;
            g_numpart[slot] = warpT[0] + warpT[1] + warpT[2] + warpT[3];
        }
    }
}

// ---------------- k2: chunk reduce + den + num + global sum (PDL secondary) ----
// one block, 1024 threads; 8 lanes per batch (128 batches x 8 chunk slots).
__global__ void __launch_bounds__(1024) k2_final(
    const float* __restrict__ dp, float* __restrict__ out)
{
    const int tid  = threadIdx.x;
    const int lane = tid & 31;
    const int wid  = tid >> 5;
    __shared__ float s_fin_sh;
    __shared__ float resv[BB];
    __shared__ float red[4];

    // dp-only prologue: overlaps k1 execution (before grid sync)
    if (wid == 0) {
        float a  = dp[lane];
        float bb = (lane + 32 < CC) ? dp[lane + 32] : NINF;
        float m = fmaxf(a, bb);
#pragma unroll
        for (int o = 16; o; o >>= 1) m = fmaxf(m, __shfl_xor_sync(0xffffffffu, m, o));
        float s = __expf(a - m) + __expf(bb - m);
#pragma unroll
        for (int o = 16; o; o >>= 1) s += __shfl_xor_sync(0xffffffffu, s, o);
        if (lane == 0) s_fin_sh = dp[LL + 2] - (m + __logf(s));
    }

    // wait for k1's gmem results to be visible
    cudaGridDependencySynchronize();

    const int b = tid >> 3;          // 0..127
    const int g = tid & 7;           // 0..7
    SMat M;
    M.p = g_cmats[b * CHB + g];
    M.e = g_cexp[b * CHB + g];
    float np = g_numpart[b * CHB + g];

#pragma unroll
    for (int s = 1; s < 8; s <<= 1) {
        SMat o = shfl_down_m(M, s, 8);
        if ((g & (2 * s - 1)) == 0) M = smul(o, M);
    }
#pragma unroll
    for (int s = 4; s; s >>= 1) np += __shfl_down_sync(0xffffffffu, np, s, 8);

    __syncthreads();   // s_fin_sh visible
    if (g == 0) {
        // alpha0=[1,0]: den = e*ln2 + log(P00) + s_fin
        float den = (float)M.e * LN2F + __logf(M.p.x) + s_fin_sh;
        resv[b] = np - den;
    }
    __syncthreads();

    float vv = (tid < BB) ? resv[tid] : 0.f;
#pragma unroll
    for (int o = 16; o; o >>= 1) vv += __shfl_xor_sync(0xffffffffu, vv, o);
    if (lane == 0 && wid < 4) red[wid] = vv;
    __syncthreads();
    if (tid == 0) out[0] = red[0] + red[1] + red[2] + red[3];
}

// ---------------- launcher ----------------
extern "C" void kernel_launch(void* const* d_in, const int* in_sizes, int n_in,
                              void* d_out, int out_size) {
    const float* lp     = (const float*)d_in[0];
    const float* dp     = (const float*)d_in[1];
    const int*   lens   = (const int*)d_in[2];
    const int*   labels = (const int*)d_in[3];

    dim3 grid(CHB, BB);
    k1_main<<<grid, 128>>>(lp, dp, lens, labels);

    // PDL launch of k2: overlaps its launch latency with k1 execution
    cudaLaunchConfig_t cfg = {};
    cfg.gridDim  = dim3(1, 1, 1);
    cfg.blockDim = dim3(1024, 1, 1);
    cfg.dynamicSmemBytes = 0;
    cfg.stream = 0;
    cudaLaunchAttribute attrs[1];
    attrs[0].id = cudaLaunchAttributeProgrammaticStreamSerialization;
    attrs[0].val.programmaticStreamSerializationAllowed = 1;
    cfg.attrs = attrs;
    cfg.numAttrs = 1;
    cudaLaunchKernelEx(&cfg, k2_final, dp, (float*)d_out);
}

// round 15
// speedup vs baseline: 1.3416x; 1.3416x over previous
#include <cuda_runtime.h>
#include <cstdint>

#define TT 4096
#define BB 128
#define CC 46
#define LL 43
#define NCH 8                 /* chunks (of 32 timesteps per warp) per block */
#define CHB 4                 /* blocks per batch = TT/(128*NCH) */
#define NINF (-3.4e38f)
#define LN2F 0.6931471805599453f

// ---------------- scratch (static device globals; no allocation) ----------------
__device__ float4 g_cmats[BB * CHB];
__device__ int    g_cexp[BB * CHB];
__device__ float  g_numpart[BB * CHB];

// ---------------- scaled-probability semiring matrix ----------------
// value = 2^e * P, P 2x2 row-major: x=00, y=01, z=10, w=11, max entry in [1,2).
struct SMat { float4 p; int e; };

// C = A (later) * B (earlier): 8 FFMA + integer exponent renorm (no MUFU).
__device__ __forceinline__ SMat smul(const SMat A, const SMat B) {
    SMat C;
    C.p.x = fmaf(A.p.x, B.p.x, A.p.y * B.p.z);
    C.p.y = fmaf(A.p.x, B.p.y, A.p.y * B.p.w);
    C.p.z = fmaf(A.p.z, B.p.x, A.p.w * B.p.z);
    C.p.w = fmaf(A.p.z, B.p.y, A.p.w * B.p.w);
    float mx = fmaxf(fmaxf(C.p.x, C.p.y), fmaxf(C.p.z, C.p.w));
    int   k  = (__float_as_int(mx) >> 23) & 255;         // biased exponent of mx
    float r  = __int_as_float((254 - k) << 23);          // exact 2^(127-k)
    C.p.x *= r; C.p.y *= r; C.p.z *= r; C.p.w *= r;
    C.e = A.e + B.e + (k - 127);
    return C;
}

__device__ __forceinline__ SMat shfl_down_m(const SMat v, int s, int w) {
    SMat r;
    r.p.x = __shfl_down_sync(0xffffffffu, v.p.x, s, w);
    r.p.y = __shfl_down_sync(0xffffffffu, v.p.y, s, w);
    r.p.z = __shfl_down_sync(0xffffffffu, v.p.z, s, w);
    r.p.w = __shfl_down_sync(0xffffffffu, v.p.w, s, w);
    r.e   = __shfl_down_sync(0xffffffffu, v.e,   s, w);
    return r;
}

__device__ __forceinline__ void cp16(uint32_t dst, const float4* src) {
    asm volatile("cp.async.cg.shared.global [%0], [%1], 16;\n" :: "r"(dst), "l"(src));
}

// FMA/ALU-pipe exp (no MUFU): magic-constant range reduction + deg-5 poly 2^r.
// Valid for log-prob inputs (finite, |x| < ~80); rel err ~2e-6.
__device__ __forceinline__ float fexp(float x) {
    const float L2E   = 1.4426950408889634f;
    const float MAGIC = 12582912.0f;          // 1.5 * 2^23
    float t = fmaf(x, L2E, MAGIC);            // integer part in low mantissa bits
    float n = t - MAGIC;                      // exact (Sterbenz)
    float r = fmaf(x, L2E, -n);               // fractional part in [-0.5, 0.5]
    float p = 1.3333558146e-3f;
    p = fmaf(p, r, 9.6181291077e-3f);
    p = fmaf(p, r, 5.5504108664e-2f);
    p = fmaf(p, r, 2.4022650696e-1f);
    p = fmaf(p, r, 6.9314718056e-1f);
    p = fmaf(p, r, 1.0f);
    return __int_as_float(__float_as_int(p) + (__float_as_int(t) << 23));
}

// ---------------- k1: warp-private pipelined streaming kernel ----------------
// grid (CHB, BB), block 128 threads. Warp w owns [t0+256w, t0+256w+256),
// processed as NCH chunks of 32 timesteps.
__global__ void __launch_bounds__(128) k1_main(
    const float* __restrict__ lp,
    const float* __restrict__ dp,
    const int* __restrict__ lens,
    const int* __restrict__ labels)
{
    __shared__ float  tiles[2][128 * CC];   // 2 x 23552 B; warp w rows [32w,32w+32)
    __shared__ float2 wab[CC];              // (w0, w1) per column; cols 0,2 zeroed
    __shared__ float  scs[2];               // [0]=exp(s_0I), [1]=exp(s_1I)
    __shared__ float4 warpP[4];
    __shared__ int    warpE[4];
    __shared__ float  warpT[4];

    const int tid  = threadIdx.x;
    const int lane = tid & 31;
    const int wid  = tid >> 5;
    const int b    = blockIdx.y;
    const int t0   = blockIdx.x * (128 * NCH);

    // warp w's 256-timestep segment: offset wid * 256 * 46 / 4 = wid * 2944 float4
    const float4* __restrict__ base4 =
        (const float4*)(lp + ((size_t)b * TT + t0) * CC) + (size_t)wid * 2944;
    const uint32_t smA = (uint32_t)__cvta_generic_to_shared(&tiles[0][0]) + wid * 368 * 16;
    const uint32_t smB = (uint32_t)__cvta_generic_to_shared(&tiles[1][0]) + wid * 368 * 16;

    // --- warp-local prefetch of chunk 0 (368 float4 per warp) ---
#pragma unroll
    for (int k = 0; k < 12; k++) {
        int i = lane + 32 * k;
        if (i < 368) cp16(smA + i * 16, base4 + i);
    }
    asm volatile("cp.async.commit_group;\n");

    // --- hoist all per-chunk label loads (coalesced; in flight early) ---
    int labv[NCH];
#pragma unroll
    for (int c = 0; c < NCH; c++)
        labv[c] = labels[(size_t)b * TT + t0 + wid * 256 + c * 32 + lane];
    const int len = lens[b];

    // --- warp 0: params (overlaps prefetch latency) ---
    if (wid == 0) {
        float a  = dp[lane];
        float bb = (lane + 32 < CC) ? dp[lane + 32] : NINF;
        float m = fmaxf(a, bb);
#pragma unroll
        for (int o = 16; o; o >>= 1) m = fmaxf(m, __shfl_xor_sync(0xffffffffu, m, o));
        float s = __expf(a - m) + __expf(bb - m);
#pragma unroll
        for (int o = 16; o; o >>= 1) s += __shfl_xor_sync(0xffffffffu, s, o);
        const float lz0 = m + __logf(s);
        float a1 = (lane < LL + 1) ? dp[CC + lane] : NINF;
        float b1 = (lane + 32 < LL + 1) ? dp[CC + lane + 32] : NINF;
        float m1 = fmaxf(a1, b1);
#pragma unroll
        for (int o = 16; o; o >>= 1) m1 = fmaxf(m1, __shfl_xor_sync(0xffffffffu, m1, o));
        float s1 = __expf(a1 - m1) + __expf(b1 - m1);
#pragma unroll
        for (int o = 16; o; o >>= 1) s1 += __shfl_xor_sync(0xffffffffu, s1, o);
        const float lz1 = m1 + __logf(s1);
#pragma unroll
        for (int c = lane; c < CC; c += 32) {
            float w0 = 0.f, w1 = 0.f;
            if (c == 1) w0 = __expf(dp[0] - lz0);          // exp(s_O): folds s_O+lp1 into S0
            if (c >= 3) {
                w0 = __expf(dp[c - 2] - lz0);              // exp(s0_lab)
                w1 = __expf(dp[CC + c - 2] - lz1);         // exp(s1_lab)
            }
            wab[c] = make_float2(w0, w1);
        }
        if (lane == 0) {
            scs[0] = __expf(dp[LL + 1] - lz0);   // exp(s_0I)
            scs[1] = __expf(dp[CC] - lz1);       // exp(s_1I)
        }
    }
    __syncthreads();   // wab/scs visible; no more block barriers until the end

    // release the dependent k2 launch as early as possible (PDL)
    cudaTriggerProgrammaticLaunchCompletion();

    const float k0 = scs[0], k1c = scs[1];
    float tok_acc = 0.f;
    SMat run;   // meaningful on lane 0 of each warp

    for (int c = 0; c < NCH; c++) {
        if (c + 1 < NCH) {
            const uint32_t dsm = ((c + 1) & 1) ? smB : smA;
            const float4* src = base4 + (size_t)(c + 1) * 368;
#pragma unroll
            for (int k = 0; k < 12; k++) {
                int i = lane + 32 * k;
                if (i < 368) cp16(dsm + i * 16, src + i);
            }
            asm volatile("cp.async.commit_group;\n");
            asm volatile("cp.async.wait_group 1;\n");
        } else {
            asm volatile("cp.async.wait_group 0;\n");
        }
        __syncwarp();   // warp-local buffer ownership

        const float* rowp = tiles[c & 1] + tid * CC;
        const int t = t0 + wid * 256 + c * 32 + lane;
        const bool valid = t < len;

        // stream 23 float2: hybrid exp — even cols MUFU, odd cols FMA-pipe poly.
        float S0a = 0.f, S0b = 0.f, S1a = 0.f, S1b = 0.f, e2 = 0.f;
        const float2* r2 = (const float2*)rowp;
#pragma unroll
        for (int i = 0; i < 23; i++) {
            float2 q = r2[i];
            float ex = __expf(q.x);                    // MUFU pipe
            float ey = fexp(q.y);                      // FMA/ALU pipes
            if (i == 1) e2 = ex;                       // exp(lp[2])
            float2 wA = wab[2 * i];
            float2 wB = wab[2 * i + 1];
            S0a = fmaf(ex, wA.x, S0a); S1a = fmaf(ex, wA.y, S1a);
            S0b = fmaf(ey, wB.x, S0b); S1b = fmaf(ey, wB.y, S1b);
        }
        tok_acc += valid ? rowp[labv[c]] : 0.f;

        SMat M;
        if (valid) {
            M.p = make_float4(S0a + S0b, S1a + S1b, e2 * k0, e2 * k1c);
        } else {
            M.p = make_float4(1.f, 0.f, 0.f, 1.f);
        }
        M.e = 0;

        // warp-level ordered fold over 32 consecutive timesteps (MUFU-free)
#pragma unroll
        for (int s = 1; s < 32; s <<= 1) {
            SMat o = shfl_down_m(M, s, 32);
            if ((lane & (2 * s - 1)) == 0) M = smul(o, M);
        }
        run = (c == 0) ? M : smul(M, run);   // valid on lane 0
    }

    // token warp sum; publish per-warp results
#pragma unroll
    for (int o = 16; o; o >>= 1) tok_acc += __shfl_xor_sync(0xffffffffu, tok_acc, o);
    if (lane == 0) { warpP[wid] = run.p; warpE[wid] = run.e; warpT[wid] = tok_acc; }
    __syncthreads();

    if (wid == 0) {
        SMat A;
        if (lane < 4) { A.p = warpP[lane]; A.e = warpE[lane]; }
        else          { A.p = make_float4(1.f, 0.f, 0.f, 1.f); A.e = 0; }
#pragma unroll
        for (int s = 1; s < 4; s <<= 1) {
            SMat o = shfl_down_m(A, s, 4);
            if ((lane & (2 * s - 1)) == 0 && lane + s < 4) A = smul(o, A);
        }
        if (lane == 0) {
            const int slot = b * CHB + blockIdx.x;
            g_cmats[slot]   = A.p;
            g_cexp[slot]    = A.e;
            g_numpart[slot] = warpT[0] + warpT[1] + warpT[2] + warpT[3];
        }
    }
}

// ---------------- k2: chunk reduce + den + num + global sum (PDL secondary) ----
// one block, 512 threads; 4 lanes per batch (128 batches x 4 chunk slots).
__global__ void __launch_bounds__(512) k2_final(
    const float* __restrict__ dp, float* __restrict__ out)
{
    const int tid  = threadIdx.x;
    const int lane = tid & 31;
    const int wid  = tid >> 5;
    __shared__ float s_fin_sh;
    __shared__ float resv[BB];
    __shared__ float red[16];

    // dp-only prologue: overlaps k1 execution (before grid sync)
    if (wid == 0) {
        float a  = dp[lane];
        float bb = (lane + 32 < CC) ? dp[lane + 32] : NINF;
        float m = fmaxf(a, bb);
#pragma unroll
        for (int o = 16; o; o >>= 1) m = fmaxf(m, __shfl_xor_sync(0xffffffffu, m, o));
        float s = __expf(a - m) + __expf(bb - m);
#pragma unroll
        for (int o = 16; o; o >>= 1) s += __shfl_xor_sync(0xffffffffu, s, o);
        if (lane == 0) s_fin_sh = dp[LL + 2] - (m + __logf(s));
    }

    // wait for k1's gmem results to be visible
    cudaGridDependencySynchronize();

    const int b = tid >> 2;          // 0..127
    const int g = tid & 3;           // 0..3
    SMat M;
    M.p = g_cmats[b * CHB + g];
    M.e = g_cexp[b * CHB + g];
    float np = g_numpart[b * CHB + g];

#pragma unroll
    for (int s = 1; s < 4; s <<= 1) {
        SMat o = shfl_down_m(M, s, 4);
        if ((g & (2 * s - 1)) == 0) M = smul(o, M);
    }
#pragma unroll
    for (int s = 2; s; s >>= 1) np += __shfl_down_sync(0xffffffffu, np, s, 4);

    __syncthreads();
    if (g == 0) {
        // alpha0=[1,0]: den = e*ln2 + log(P00) + s_fin
        float den = (float)M.e * LN2F + __logf(M.p.x) + s_fin_sh;
        resv[b] = np - den;
    }
    __syncthreads();

    float vv = (tid < BB) ? resv[tid] : 0.f;
#pragma unroll
    for (int o = 16; o; o >>= 1) vv += __shfl_xor_sync(0xffffffffu, vv, o);
    if (lane == 0) red[wid] = vv;
    __syncthreads();
    if (tid == 0) {
        float tsum = 0.f;
#pragma unroll
        for (int i = 0; i < 4; i++) tsum += red[i];   // warps 0-3 hold the BB values
        out[0] = tsum;
    }
}

// ---------------- launcher ----------------
extern "C" void kernel_launch(void* const* d_in, const int* in_sizes, int n_in,
                              void* d_out, int out_size) {
    const float* lp     = (const float*)d_in[0];
    const float* dp     = (const float*)d_in[1];
    const int*   lens   = (const int*)d_in[2];
    const int*   labels = (const int*)d_in[3];

    dim3 grid(CHB, BB);
    k1_main<<<grid, 128>>>(lp, dp, lens, labels);

    // PDL launch of k2: overlaps its launch latency with k1 execution
    cudaLaunchConfig_t cfg = {};
    cfg.gridDim  = dim3(1, 1, 1);
    cfg.blockDim = dim3(512, 1, 1);
    cfg.dynamicSmemBytes = 0;
    cfg.stream = 0;
    cudaLaunchAttribute attrs[1];
    attrs[0].id = cudaLaunchAttributeProgrammaticStreamSerialization;
    attrs[0].val.programmaticStreamSerializationAllowed = 1;
    cfg.attrs = attrs;
    cfg.numAttrs = 1;
    cudaLaunchKernelEx(&cfg, k2_final, dp, (float*)d_out);
}

// round 16
// speedup vs baseline: 1.3453x; 1.0028x over previous
#include <cuda_runtime.h>
#include <cstdint>

#define TT 4096
#define BB 128
#define CC 46
#define LL 43
#define NCH 8                 /* chunks (of 32 timesteps per warp) per block */
#define CHB 4                 /* worker blocks per batch = TT/(128*NCH) */
#define NW  (BB * CHB)        /* 512 worker blocks */
#define NINF (-3.4e38f)
#define LN2F 0.6931471805599453f

// ---------------- scratch (static device globals; no allocation) ----------------
__device__ float4 g_cmats[NW];
__device__ int    g_cexp[NW];
__device__ float  g_numpart[NW];
__device__ int    g_cnt;              // zero-init (BSS); closer resets each run

// ---------------- scaled-probability semiring matrix ----------------
// value = 2^e * P, P 2x2 row-major: x=00, y=01, z=10, w=11, max entry in [1,2).
struct SMat { float4 p; int e; };

// C = A (later) * B (earlier): 8 FFMA + integer exponent renorm (no MUFU).
__device__ __forceinline__ SMat smul(const SMat A, const SMat B) {
    SMat C;
    C.p.x = fmaf(A.p.x, B.p.x, A.p.y * B.p.z);
    C.p.y = fmaf(A.p.x, B.p.y, A.p.y * B.p.w);
    C.p.z = fmaf(A.p.z, B.p.x, A.p.w * B.p.z);
    C.p.w = fmaf(A.p.z, B.p.y, A.p.w * B.p.w);
    float mx = fmaxf(fmaxf(C.p.x, C.p.y), fmaxf(C.p.z, C.p.w));
    int   k  = (__float_as_int(mx) >> 23) & 255;         // biased exponent of mx
    float r  = __int_as_float((254 - k) << 23);          // exact 2^(127-k)
    C.p.x *= r; C.p.y *= r; C.p.z *= r; C.p.w *= r;
    C.e = A.e + B.e + (k - 127);
    return C;
}

__device__ __forceinline__ SMat shfl_down_m(const SMat v, int s, int w) {
    SMat r;
    r.p.x = __shfl_down_sync(0xffffffffu, v.p.x, s, w);
    r.p.y = __shfl_down_sync(0xffffffffu, v.p.y, s, w);
    r.p.z = __shfl_down_sync(0xffffffffu, v.p.z, s, w);
    r.p.w = __shfl_down_sync(0xffffffffu, v.p.w, s, w);
    r.e   = __shfl_down_sync(0xffffffffu, v.e,   s, w);
    return r;
}

__device__ __forceinline__ void cp16(uint32_t dst, const float4* src) {
    asm volatile("cp.async.cg.shared.global [%0], [%1], 16;\n" :: "r"(dst), "l"(src));
}

// ---------------- fused kernel: 512 workers + 1 spin-closer block ----------------
__global__ void __launch_bounds__(128) k1_main(
    const float* __restrict__ lp,
    const float* __restrict__ dp,
    const int* __restrict__ lens,
    const int* __restrict__ labels,
    float* __restrict__ out)
{
    __shared__ float  tiles[2][128 * CC];   // 2 x 23552 B; warp w rows [32w,32w+32)
    __shared__ float2 wab[CC];              // (w0, w1) per column; cols 0,2 zeroed
    __shared__ float  scs[2];               // workers: exp(s_0I), exp(s_1I); closer: s_fin
    __shared__ float4 warpP[4];
    __shared__ int    warpE[4];
    __shared__ float  warpT[4];

    const int tid  = threadIdx.x;
    const int lane = tid & 31;
    const int wid  = tid >> 5;

    // ================= closer block =================
    if (blockIdx.x == NW) {
        // dp prologue: s_fin = g0[LL+2] (computed while workers run)
        if (wid == 0) {
            float a  = dp[lane];
            float bb = (lane + 32 < CC) ? dp[lane + 32] : NINF;
            float m = fmaxf(a, bb);
#pragma unroll
            for (int o = 16; o; o >>= 1) m = fmaxf(m, __shfl_xor_sync(0xffffffffu, m, o));
            float s = __expf(a - m) + __expf(bb - m);
#pragma unroll
            for (int o = 16; o; o >>= 1) s += __shfl_xor_sync(0xffffffffu, s, o);
            if (lane == 0) scs[0] = dp[LL + 2] - (m + __logf(s));   // s_fin
        }
        // spin until all workers published
        if (tid == 0) {
            while (atomicAdd(&g_cnt, 0) < NW) __nanosleep(64);
            __threadfence();
        }
        __syncthreads();

        // thread tid = batch tid: fold its CHB chunk matrices (time-ascending)
        const int bb2 = tid;
        SMat M;
        M.p = g_cmats[bb2 * CHB];
        M.e = g_cexp[bb2 * CHB];
        float np = g_numpart[bb2 * CHB];
#pragma unroll
        for (int j = 1; j < CHB; j++) {
            SMat Nx;
            Nx.p = g_cmats[bb2 * CHB + j];
            Nx.e = g_cexp[bb2 * CHB + j];
            M = smul(Nx, M);                  // later x earlier
            np += g_numpart[bb2 * CHB + j];
        }
        // alpha0=[1,0]: den = e*ln2 + log(P00) + s_fin
        float val = np - ((float)M.e * LN2F + __logf(M.p.x) + scs[0]);

        // block sum of 128 values
#pragma unroll
        for (int o = 16; o; o >>= 1) val += __shfl_xor_sync(0xffffffffu, val, o);
        if (lane == 0) warpT[wid] = val;
        __syncthreads();
        if (tid == 0) {
            out[0] = warpT[0] + warpT[1] + warpT[2] + warpT[3];
            g_cnt = 0;                        // reset for next graph replay
        }
        return;
    }

    // ================= worker blocks (R10 hot path, unchanged) =================
    const int b    = blockIdx.x >> 2;         // batch
    const int cx   = blockIdx.x & 3;          // chunk-block within batch
    const int t0   = cx * (128 * NCH);

    // warp w's 256-timestep segment: offset wid * 256 * 46 / 4 = wid * 2944 float4
    const float4* __restrict__ base4 =
        (const float4*)(lp + ((size_t)b * TT + t0) * CC) + (size_t)wid * 2944;
    const uint32_t smA = (uint32_t)__cvta_generic_to_shared(&tiles[0][0]) + wid * 368 * 16;
    const uint32_t smB = (uint32_t)__cvta_generic_to_shared(&tiles[1][0]) + wid * 368 * 16;

    // --- warp-local prefetch of chunk 0 (368 float4 per warp) ---
#pragma unroll
    for (int k = 0; k < 12; k++) {
        int i = lane + 32 * k;
        if (i < 368) cp16(smA + i * 16, base4 + i);
    }
    asm volatile("cp.async.commit_group;\n");

    // --- warp 0: params (overlaps prefetch latency) ---
    if (wid == 0) {
        float a  = dp[lane];
        float bb = (lane + 32 < CC) ? dp[lane + 32] : NINF;
        float m = fmaxf(a, bb);
#pragma unroll
        for (int o = 16; o; o >>= 1) m = fmaxf(m, __shfl_xor_sync(0xffffffffu, m, o));
        float s = __expf(a - m) + __expf(bb - m);
#pragma unroll
        for (int o = 16; o; o >>= 1) s += __shfl_xor_sync(0xffffffffu, s, o);
        const float lz0 = m + __logf(s);
        float a1 = (lane < LL + 1) ? dp[CC + lane] : NINF;
        float b1 = (lane + 32 < LL + 1) ? dp[CC + lane + 32] : NINF;
        float m1 = fmaxf(a1, b1);
#pragma unroll
        for (int o = 16; o; o >>= 1) m1 = fmaxf(m1, __shfl_xor_sync(0xffffffffu, m1, o));
        float s1 = __expf(a1 - m1) + __expf(b1 - m1);
#pragma unroll
        for (int o = 16; o; o >>= 1) s1 += __shfl_xor_sync(0xffffffffu, s1, o);
        const float lz1 = m1 + __logf(s1);
#pragma unroll
        for (int c = lane; c < CC; c += 32) {
            float w0 = 0.f, w1 = 0.f;
            if (c == 1) w0 = __expf(dp[0] - lz0);          // exp(s_O): folds s_O+lp1 into S0
            if (c >= 3) {
                w0 = __expf(dp[c - 2] - lz0);              // exp(s0_lab)
                w1 = __expf(dp[CC + c - 2] - lz1);         // exp(s1_lab)
            }
            wab[c] = make_float2(w0, w1);
        }
        if (lane == 0) {
            scs[0] = __expf(dp[LL + 1] - lz0);   // exp(s_0I)
            scs[1] = __expf(dp[CC] - lz1);       // exp(s_1I)
        }
    }
    __syncthreads();   // wab/scs visible; no more block barriers until the end

    const int len = lens[b];
    const float k0 = scs[0], k1c = scs[1];
    float tok_acc = 0.f;
    SMat run;   // meaningful on lane 0 of each warp

    for (int c = 0; c < NCH; c++) {
        if (c + 1 < NCH) {
            const uint32_t dsm = ((c + 1) & 1) ? smB : smA;
            const float4* src = base4 + (size_t)(c + 1) * 368;
#pragma unroll
            for (int k = 0; k < 12; k++) {
                int i = lane + 32 * k;
                if (i < 368) cp16(dsm + i * 16, src + i);
            }
            asm volatile("cp.async.commit_group;\n");
            asm volatile("cp.async.wait_group 1;\n");
        } else {
            asm volatile("cp.async.wait_group 0;\n");
        }
        __syncwarp();   // warp-local buffer ownership

        const float* rowp = tiles[c & 1] + tid * CC;
        const int t = t0 + wid * 256 + c * 32 + lane;
        const int lab = labels[(size_t)b * TT + t];
        const bool valid = t < len;

        // stream 23 float2: exp directly (log-softmax inputs <= 0: no overflow)
        float S0a = 0.f, S0b = 0.f, S1a = 0.f, S1b = 0.f, e2 = 0.f;
        const float2* r2 = (const float2*)rowp;
#pragma unroll
        for (int i = 0; i < 23; i++) {
            float2 q = r2[i];
            float ex = __expf(q.x);
            float ey = __expf(q.y);
            if (i == 1) e2 = ex;                       // exp(lp[2])
            float2 wA = wab[2 * i];
            float2 wB = wab[2 * i + 1];
            S0a = fmaf(ex, wA.x, S0a); S1a = fmaf(ex, wA.y, S1a);
            S0b = fmaf(ey, wB.x, S0b); S1b = fmaf(ey, wB.y, S1b);
        }
        tok_acc += valid ? rowp[lab] : 0.f;

        SMat M;
        if (valid) {
            M.p = make_float4(S0a + S0b, S1a + S1b, e2 * k0, e2 * k1c);
        } else {
            M.p = make_float4(1.f, 0.f, 0.f, 1.f);
        }
        M.e = 0;

        // warp-level ordered fold over 32 consecutive timesteps (MUFU-free)
#pragma unroll
        for (int s = 1; s < 32; s <<= 1) {
            SMat o = shfl_down_m(M, s, 32);
            if ((lane & (2 * s - 1)) == 0) M = smul(o, M);
        }
        run = (c == 0) ? M : smul(M, run);   // valid on lane 0
    }

    // token warp sum; publish per-warp results
#pragma unroll
    for (int o = 16; o; o >>= 1) tok_acc += __shfl_xor_sync(0xffffffffu, tok_acc, o);
    if (lane == 0) { warpP[wid] = run.p; warpE[wid] = run.e; warpT[wid] = tok_acc; }
    __syncthreads();

    if (wid == 0) {
        SMat A;
        if (lane < 4) { A.p = warpP[lane]; A.e = warpE[lane]; }
        else          { A.p = make_float4(1.f, 0.f, 0.f, 1.f); A.e = 0; }
#pragma unroll
        for (int s = 1; s < 4; s <<= 1) {
            SMat o = shfl_down_m(A, s, 4);
            if ((lane & (2 * s - 1)) == 0 && lane + s < 4) A = smul(o, A);
        }
        if (lane == 0) {
            const int slot = b * CHB + cx;
            g_cmats[slot]   = A.p;
            g_cexp[slot]    = A.e;
            g_numpart[slot] = warpT[0] + warpT[1] + warpT[2] + warpT[3];
            __threadfence();                  // publish before signaling
            atomicAdd(&g_cnt, 1);
        }
    }
}

// ---------------- launcher ----------------
extern "C" void kernel_launch(void* const* d_in, const int* in_sizes, int n_in,
                              void* d_out, int out_size) {
    const float* lp     = (const float*)d_in[0];
    const float* dp     = (const float*)d_in[1];
    const int*   lens   = (const int*)d_in[2];
    const int*   labels = (const int*)d_in[3];

    k1_main<<<NW + 1, 128>>>(lp, dp, lens, labels, (float*)d_out);
}

// round 17
// speedup vs baseline: 1.4909x; 1.1082x over previous
#include <cuda_runtime.h>
#include <cstdint>

#define TT 4096
#define BB 128
#define CC 46
#define LL 43
#define NCH 8                 /* chunks (of 32 timesteps per warp) per block */
#define CHB 4                 /* blocks per batch = TT/(128*NCH) */
#define NINF (-3.4e38f)
#define LN2F 0.6931471805599453f

// ---------------- scratch (static device globals; no allocation) ----------------
__device__ float4 g_cmats[BB * CHB];
__device__ int    g_cexp[BB * CHB];
__device__ float  g_numpart[BB * CHB];

// ---------------- scaled-probability semiring matrix ----------------
// value = 2^e * P, P 2x2 row-major: x=00, y=01, z=10, w=11, max entry in [1,2).
struct SMat { float4 p; int e; };

// C = A (later) * B (earlier): 8 FFMA + integer exponent renorm (no MUFU).
__device__ __forceinline__ SMat smul(const SMat A, const SMat B) {
    SMat C;
    C.p.x = fmaf(A.p.x, B.p.x, A.p.y * B.p.z);
    C.p.y = fmaf(A.p.x, B.p.y, A.p.y * B.p.w);
    C.p.z = fmaf(A.p.z, B.p.x, A.p.w * B.p.z);
    C.p.w = fmaf(A.p.z, B.p.y, A.p.w * B.p.w);
    float mx = fmaxf(fmaxf(C.p.x, C.p.y), fmaxf(C.p.z, C.p.w));
    int   k  = (__float_as_int(mx) >> 23) & 255;         // biased exponent of mx
    float r  = __int_as_float((254 - k) << 23);          // exact 2^(127-k)
    C.p.x *= r; C.p.y *= r; C.p.z *= r; C.p.w *= r;
    C.e = A.e + B.e + (k - 127);
    return C;
}

__device__ __forceinline__ SMat shfl_down_m(const SMat v, int s, int w) {
    SMat r;
    r.p.x = __shfl_down_sync(0xffffffffu, v.p.x, s, w);
    r.p.y = __shfl_down_sync(0xffffffffu, v.p.y, s, w);
    r.p.z = __shfl_down_sync(0xffffffffu, v.p.z, s, w);
    r.p.w = __shfl_down_sync(0xffffffffu, v.p.w, s, w);
    r.e   = __shfl_down_sync(0xffffffffu, v.e,   s, w);
    return r;
}

__device__ __forceinline__ void cp16(uint32_t dst, const float4* src) {
    asm volatile("cp.async.cg.shared.global [%0], [%1], 16;\n" :: "r"(dst), "l"(src));
}

// ---------------- k1: warp-private pipelined streaming kernel ----------------
// grid (CHB, BB), block 128 threads. Warp w owns [t0+256w, t0+256w+256),
// processed as NCH chunks of 32 timesteps.
__global__ void __launch_bounds__(128) k1_main(
    const float* __restrict__ lp,
    const float* __restrict__ dp,
    const int* __restrict__ lens,
    const int* __restrict__ labels)
{
    __shared__ float  tiles[2][128 * CC];   // 2 x 23552 B; warp w rows [32w,32w+32)
    __shared__ float2 wab[CC];              // (w0, w1) per column; cols 0,2 zeroed
    __shared__ float  scs[2];               // [0]=exp(s_0I), [1]=exp(s_1I)
    __shared__ float4 warpP[4];
    __shared__ int    warpE[4];
    __shared__ float  warpT[4];

    const int tid  = threadIdx.x;
    const int lane = tid & 31;
    const int wid  = tid >> 5;
    const int b    = blockIdx.y;
    const int t0   = blockIdx.x * (128 * NCH);

    // warp w's 256-timestep segment: offset wid * 256 * 46 / 4 = wid * 2944 float4
    const float4* __restrict__ base4 =
        (const float4*)(lp + ((size_t)b * TT + t0) * CC) + (size_t)wid * 2944;
    const uint32_t smA = (uint32_t)__cvta_generic_to_shared(&tiles[0][0]) + wid * 368 * 16;
    const uint32_t smB = (uint32_t)__cvta_generic_to_shared(&tiles[1][0]) + wid * 368 * 16;

    // --- warp-local prefetch of chunk 0 (368 float4 per warp) ---
#pragma unroll
    for (int k = 0; k < 12; k++) {
        int i = lane + 32 * k;
        if (i < 368) cp16(smA + i * 16, base4 + i);
    }
    asm volatile("cp.async.commit_group;\n");

    // --- hoist per-chunk label loads: MLP=8, overlapped with first prefetch ---
    int labv[NCH];
#pragma unroll
    for (int c = 0; c < NCH; c++)
        labv[c] = labels[(size_t)b * TT + t0 + wid * 256 + c * 32 + lane];
    const int len = lens[b];

    // --- warp 0: params (overlaps prefetch latency) ---
    if (wid == 0) {
        float a  = dp[lane];
        float bb = (lane + 32 < CC) ? dp[lane + 32] : NINF;
        float m = fmaxf(a, bb);
#pragma unroll
        for (int o = 16; o; o >>= 1) m = fmaxf(m, __shfl_xor_sync(0xffffffffu, m, o));
        float s = __expf(a - m) + __expf(bb - m);
#pragma unroll
        for (int o = 16; o; o >>= 1) s += __shfl_xor_sync(0xffffffffu, s, o);
        const float lz0 = m + __logf(s);
        float a1 = (lane < LL + 1) ? dp[CC + lane] : NINF;
        float b1 = (lane + 32 < LL + 1) ? dp[CC + lane + 32] : NINF;
        float m1 = fmaxf(a1, b1);
#pragma unroll
        for (int o = 16; o; o >>= 1) m1 = fmaxf(m1, __shfl_xor_sync(0xffffffffu, m1, o));
        float s1 = __expf(a1 - m1) + __expf(b1 - m1);
#pragma unroll
        for (int o = 16; o; o >>= 1) s1 += __shfl_xor_sync(0xffffffffu, s1, o);
        const float lz1 = m1 + __logf(s1);
#pragma unroll
        for (int c = lane; c < CC; c += 32) {
            float w0 = 0.f, w1 = 0.f;
            if (c == 1) w0 = __expf(dp[0] - lz0);          // exp(s_O): folds s_O+lp1 into S0
            if (c >= 3) {
                w0 = __expf(dp[c - 2] - lz0);              // exp(s0_lab)
                w1 = __expf(dp[CC + c - 2] - lz1);         // exp(s1_lab)
            }
            wab[c] = make_float2(w0, w1);
        }
        if (lane == 0) {
            scs[0] = __expf(dp[LL + 1] - lz0);   // exp(s_0I)
            scs[1] = __expf(dp[CC] - lz1);       // exp(s_1I)
        }
    }
    __syncthreads();   // wab/scs visible; no more block barriers until the end

    // release the dependent k2 launch as early as possible (PDL)
    cudaTriggerProgrammaticLaunchCompletion();

    const float k0 = scs[0], k1c = scs[1];
    float tok_acc = 0.f;
    SMat run;   // meaningful on lane 0 of each warp

    for (int c = 0; c < NCH; c++) {
        if (c + 1 < NCH) {
            const uint32_t dsm = ((c + 1) & 1) ? smB : smA;
            const float4* src = base4 + (size_t)(c + 1) * 368;
#pragma unroll
            for (int k = 0; k < 12; k++) {
                int i = lane + 32 * k;
                if (i < 368) cp16(dsm + i * 16, src + i);
            }
            asm volatile("cp.async.commit_group;\n");
            asm volatile("cp.async.wait_group 1;\n");
        } else {
            asm volatile("cp.async.wait_group 0;\n");
        }
        __syncwarp();   // warp-local buffer ownership

        const float* rowp = tiles[c & 1] + tid * CC;
        const int t = t0 + wid * 256 + c * 32 + lane;
        const bool valid = t < len;

        // stream float2 pairs: exp directly (log-softmax inputs <= 0: no overflow).
        // i=0 special-cased: col 0 has zero weight, so its exp is skipped.
        const float2* r2 = (const float2*)rowp;
        float2 q0 = r2[0];
        float  ey0 = __expf(q0.y);                 // col 1 (s_O path)
        float2 wB0 = wab[1];
        float S0a = 0.f,            S0b = ey0 * wB0.x;
        float S1a = 0.f,            S1b = ey0 * wB0.y;
        float e2 = 0.f;
#pragma unroll
        for (int i = 1; i < 23; i++) {
            float2 q = r2[i];
            float ex = __expf(q.x);
            float ey = __expf(q.y);
            if (i == 1) e2 = ex;                   // exp(lp[2]); wab[2]=(0,0)
            float2 wA = wab[2 * i];
            float2 wB = wab[2 * i + 1];
            S0a = fmaf(ex, wA.x, S0a); S1a = fmaf(ex, wA.y, S1a);
            S0b = fmaf(ey, wB.x, S0b); S1b = fmaf(ey, wB.y, S1b);
        }
        tok_acc += valid ? rowp[labv[c]] : 0.f;

        SMat M;
        if (valid) {
            M.p = make_float4(S0a + S0b, S1a + S1b, e2 * k0, e2 * k1c);
        } else {
            M.p = make_float4(1.f, 0.f, 0.f, 1.f);
        }
        M.e = 0;

        // warp-level ordered fold over 32 consecutive timesteps (MUFU-free)
#pragma unroll
        for (int s = 1; s < 32; s <<= 1) {
            SMat o = shfl_down_m(M, s, 32);
            if ((lane & (2 * s - 1)) == 0) M = smul(o, M);
        }
        run = (c == 0) ? M : smul(M, run);   // valid on lane 0
    }

    // token warp sum; publish per-warp results
#pragma unroll
    for (int o = 16; o; o >>= 1) tok_acc += __shfl_xor_sync(0xffffffffu, tok_acc, o);
    if (lane == 0) { warpP[wid] = run.p; warpE[wid] = run.e; warpT[wid] = tok_acc; }
    __syncthreads();

    if (wid == 0) {
        SMat A;
        if (lane < 4) { A.p = warpP[lane]; A.e = warpE[lane]; }
        else          { A.p = make_float4(1.f, 0.f, 0.f, 1.f); A.e = 0; }
#pragma unroll
        for (int s = 1; s < 4; s <<= 1) {
            SMat o = shfl_down_m(A, s, 4);
            if ((lane & (2 * s - 1)) == 0 && lane + s < 4) A = smul(o, A);
        }
        if (lane == 0) {
            const int slot = b * CHB + blockIdx.x;
            g_cmats[slot]   = A.p;
            g_cexp[slot]    = A.e;
            g_numpart[slot] = warpT[0] + warpT[1] + warpT[2] + warpT[3];
        }
    }
}

// ---------------- k2: chunk reduce + den + num + global sum (PDL secondary) ----
// one block, 512 threads; 4 lanes per batch (128 batches x 4 chunk slots).
__global__ void __launch_bounds__(512) k2_final(
    const float* __restrict__ dp, float* __restrict__ out)
{
    const int tid  = threadIdx.x;
    const int lane = tid & 31;
    const int wid  = tid >> 5;
    __shared__ float s_fin_sh;
    __shared__ float resv[BB];
    __shared__ float red[16];

    // dp-only prologue: overlaps k1 execution (before grid sync)
    if (wid == 0) {
        float a  = dp[lane];
        float bb = (lane + 32 < CC) ? dp[lane + 32] : NINF;
        float m = fmaxf(a, bb);
#pragma unroll
        for (int o = 16; o; o >>= 1) m = fmaxf(m, __shfl_xor_sync(0xffffffffu, m, o));
        float s = __expf(a - m) + __expf(bb - m);
#pragma unroll
        for (int o = 16; o; o >>= 1) s += __shfl_xor_sync(0xffffffffu, s, o);
        if (lane == 0) s_fin_sh = dp[LL + 2] - (m + __logf(s));
    }

    // wait for k1's gmem results to be visible
    cudaGridDependencySynchronize();

    const int b = tid >> 2;          // 0..127
    const int g = tid & 3;           // 0..3
    SMat M;
    M.p = g_cmats[b * CHB + g];
    M.e = g_cexp[b * CHB + g];
    float np = g_numpart[b * CHB + g];

#pragma unroll
    for (int s = 1; s < 4; s <<= 1) {
        SMat o = shfl_down_m(M, s, 4);
        if ((g & (2 * s - 1)) == 0) M = smul(o, M);
    }
#pragma unroll
    for (int s = 2; s; s >>= 1) np += __shfl_down_sync(0xffffffffu, np, s, 4);

    __syncthreads();
    if (g == 0) {
        // alpha0=[1,0]: den = e*ln2 + log(P00) + s_fin
        float den = (float)M.e * LN2F + __logf(M.p.x) + s_fin_sh;
        resv[b] = np - den;
    }
    __syncthreads();

    float vv = (tid < BB) ? resv[tid] : 0.f;
#pragma unroll
    for (int o = 16; o; o >>= 1) vv += __shfl_xor_sync(0xffffffffu, vv, o);
    if (lane == 0) red[wid] = vv;
    __syncthreads();
    if (tid == 0) {
        float tsum = 0.f;
#pragma unroll
        for (int i = 0; i < 4; i++) tsum += red[i];   // warps 0-3 hold the BB values
        out[0] = tsum;
    }
}

// ---------------- launcher ----------------
extern "C" void kernel_launch(void* const* d_in, const int* in_sizes, int n_in,
                              void* d_out, int out_size) {
    const float* lp     = (const float*)d_in[0];
    const float* dp     = (const float*)d_in[1];
    const int*   lens   = (const int*)d_in[2];
    const int*   labels = (const int*)d_in[3];

    dim3 grid(CHB, BB);
    k1_main<<<grid, 128>>>(lp, dp, lens, labels);

    // PDL launch of k2: overlaps its launch latency with k1 execution
    cudaLaunchConfig_t cfg = {};
    cfg.gridDim  = dim3(1, 1, 1);
    cfg.blockDim = dim3(512, 1, 1);
    cfg.dynamicSmemBytes = 0;
    cfg.stream = 0;
    cudaLaunchAttribute attrs[1];
    attrs[0].id = cudaLaunchAttributeProgrammaticStreamSerialization;
    attrs[0].val.programmaticStreamSerializationAllowed = 1;
    cfg.attrs = attrs;
    cfg.numAttrs = 1;
    cudaLaunchKernelEx(&cfg, k2_final, dp, (float*)d_out);
}